// round 1
// baseline (speedup 1.0000x reference)
#include <cuda_runtime.h>

#define T_TOTAL 8192
#define DIM     128
#define CHUNK   64
#define NCHUNK  (T_TOTAL / CHUNK)   // 128 chunks
#define CPS     16                  // chunks per sequence (1024 / 64)

#define KT_PITCH 65
#define S_PITCH  65

// Scratch (no cudaMalloc allowed): per-chunk Gram matrices and prefix states.
__device__ float g_G[NCHUNK][DIM][DIM];    // K_c^T V_c            (8 MB)
__device__ float g_Min[NCHUNK][DIM][DIM];  // state entering chunk (8 MB)

// ---------------------------------------------------------------------------
// Kernel 1: G_c = K_c^T V_c for every chunk (fully parallel, 128 blocks).
// Streamed dim = t (rows of K,V): both operands read row-wise as float4.
// ---------------------------------------------------------------------------
__global__ void __launch_bounds__(256) la_kv_kernel(const float* __restrict__ Kg,
                                                    const float* __restrict__ Vg) {
    extern __shared__ float sm[];
    float* sK = sm;                 // [CHUNK][DIM]
    float* sV = sm + CHUNK * DIM;   // [CHUNK][DIM]
    const int c   = blockIdx.x;
    const int tid = threadIdx.x;

    const float4* gk = (const float4*)(Kg + (size_t)c * CHUNK * DIM);
    const float4* gv = (const float4*)(Vg + (size_t)c * CHUNK * DIM);
    float4* sk4 = (float4*)sK;
    float4* sv4 = (float4*)sV;
#pragma unroll
    for (int i = tid; i < CHUNK * DIM / 4; i += 256) {
        sk4[i] = gk[i];
        sv4[i] = gv[i];
    }
    __syncthreads();

    const int i0 = (tid >> 4) * 8;   // output row block   (K-feature index)
    const int j0 = (tid & 15) * 8;   // output col block   (V-feature index)

    float acc[8][8];
#pragma unroll
    for (int u = 0; u < 8; u++)
#pragma unroll
        for (int w = 0; w < 8; w++) acc[u][w] = 0.f;

#pragma unroll 4
    for (int t = 0; t < CHUNK; ++t) {
        float4 a0 = *(const float4*)&sK[t * DIM + i0];
        float4 a1 = *(const float4*)&sK[t * DIM + i0 + 4];
        float4 b0 = *(const float4*)&sV[t * DIM + j0];
        float4 b1 = *(const float4*)&sV[t * DIM + j0 + 4];
        float a[8] = {a0.x, a0.y, a0.z, a0.w, a1.x, a1.y, a1.z, a1.w};
        float b[8] = {b0.x, b0.y, b0.z, b0.w, b1.x, b1.y, b1.z, b1.w};
#pragma unroll
        for (int u = 0; u < 8; u++)
#pragma unroll
            for (int w = 0; w < 8; w++) acc[u][w] += a[u] * b[w];
    }

    float* gG = &g_G[c][0][0];
#pragma unroll
    for (int u = 0; u < 8; u++) {
        *(float4*)&gG[(i0 + u) * DIM + j0]     = make_float4(acc[u][0], acc[u][1], acc[u][2], acc[u][3]);
        *(float4*)&gG[(i0 + u) * DIM + j0 + 4] = make_float4(acc[u][4], acc[u][5], acc[u][6], acc[u][7]);
    }
}

// ---------------------------------------------------------------------------
// Kernel 2: per-sequence prefix sum of G into M_in (M_in[first chunk] = M_0).
// grid = (32, 8): 8 sequences x (4096 float4 elements / 128 threads).
// ---------------------------------------------------------------------------
__global__ void __launch_bounds__(128) la_prefix_kernel(const float* __restrict__ M0) {
    const int e   = blockIdx.x * 128 + threadIdx.x;  // float4 element index 0..4095
    const int c0  = blockIdx.y * CPS;                // first chunk of this sequence
    float4 m = ((const float4*)M0)[e];
#pragma unroll
    for (int cl = 0; cl < CPS; ++cl) {
        ((float4*)&g_Min[c0 + cl][0][0])[e] = m;
        float4 g = ((const float4*)&g_G[c0 + cl][0][0])[e];
        m.x += g.x; m.y += g.y; m.z += g.z; m.w += g.w;
    }
}

// ---------------------------------------------------------------------------
// Kernel 3: per chunk  O = Q*M_in + tril_incl(Q K^T) * V   (128 blocks).
// Phase A: S = masked Q K^T using transposed-K smem staging (row-wise stream).
// Phase B: O accumulated over both S*V (s-loop) and Q*M_in (k-loop, M_in from
//          global, L1-resident).
// ---------------------------------------------------------------------------
__global__ void __launch_bounds__(256) la_attn_kernel(const float* __restrict__ Qg,
                                                      const float* __restrict__ Kg,
                                                      const float* __restrict__ Vg,
                                                      float* __restrict__ Og) {
    extern __shared__ float sm[];
    float* sQ  = sm;                       // [64][128]
    float* sV  = sQ + CHUNK * DIM;         // [64][128]
    float* sKt = sV + CHUNK * DIM;         // [128][KT_PITCH]  K transposed
    float* sS  = sKt + DIM * KT_PITCH;     // [64][S_PITCH]    masked scores

    const int c    = blockIdx.x;
    const int tid  = threadIdx.x;
    const int wid  = tid >> 5;
    const int lane = tid & 31;

    const float4* gq = (const float4*)(Qg + (size_t)c * CHUNK * DIM);
    const float4* gv = (const float4*)(Vg + (size_t)c * CHUNK * DIM);
    const float4* gk = (const float4*)(Kg + (size_t)c * CHUNK * DIM);

#pragma unroll
    for (int i = tid; i < CHUNK * DIM / 4; i += 256) {
        ((float4*)sQ)[i] = gq[i];
        ((float4*)sV)[i] = gv[i];
    }
    // K transposed into smem: sKt[k][t] = K[t][k]
#pragma unroll
    for (int f = tid; f < CHUNK * DIM / 4; f += 256) {
        int t  = f >> 5;              // token row (128 floats = 32 float4 per row)
        int k0 = (f & 31) << 2;       // feature base
        float4 kv = gk[f];
        sKt[(k0 + 0) * KT_PITCH + t] = kv.x;
        sKt[(k0 + 1) * KT_PITCH + t] = kv.y;
        sKt[(k0 + 2) * KT_PITCH + t] = kv.z;
        sKt[(k0 + 3) * KT_PITCH + t] = kv.w;
    }
    __syncthreads();

    // --- Phase A: S[t][s] = sum_k Q[t][k] K[s][k], inclusive causal (s <= t)
    {
        const int t0 = wid * 8;       // each warp owns 8 output rows
        float accA[8][2];
#pragma unroll
        for (int u = 0; u < 8; u++) { accA[u][0] = 0.f; accA[u][1] = 0.f; }
#pragma unroll 2
        for (int k = 0; k < DIM; k++) {
            float b0 = sKt[k * KT_PITCH + lane];        // s = lane
            float b1 = sKt[k * KT_PITCH + 32 + lane];   // s = lane + 32
#pragma unroll
            for (int u = 0; u < 8; u++) {
                float a = sQ[(t0 + u) * DIM + k];       // warp-broadcast
                accA[u][0] += a * b0;
                accA[u][1] += a * b1;
            }
        }
#pragma unroll
        for (int u = 0; u < 8; u++) {
            int t = t0 + u;
            sS[t * S_PITCH + lane]      = (lane <= t)        ? accA[u][0] : 0.f;
            sS[t * S_PITCH + 32 + lane] = ((32 + lane) <= t) ? accA[u][1] : 0.f;
        }
    }
    __syncthreads();

    // --- Phase B: O[t][j] = sum_s S[t][s] V[s][j] + sum_k Q[t][k] Min[k][j]
    const int t0 = wid * 8;           // warp owns 8 rows; lane owns 4 cols
    float acc[8][4];
#pragma unroll
    for (int u = 0; u < 8; u++)
#pragma unroll
        for (int w = 0; w < 4; w++) acc[u][w] = 0.f;

#pragma unroll 2
    for (int s = 0; s < CHUNK; s++) {
        float4 b = *(const float4*)&sV[s * DIM + lane * 4];
#pragma unroll
        for (int u = 0; u < 8; u++) {
            float a = sS[(t0 + u) * S_PITCH + s];       // warp-broadcast
            acc[u][0] += a * b.x;
            acc[u][1] += a * b.y;
            acc[u][2] += a * b.z;
            acc[u][3] += a * b.w;
        }
    }

    const float4* gM = (const float4*)&g_Min[c][0][0];
#pragma unroll 2
    for (int k = 0; k < DIM; k++) {
        float4 b = gM[k * (DIM / 4) + lane];            // coalesced, L1-hot
#pragma unroll
        for (int u = 0; u < 8; u++) {
            float a = sQ[(t0 + u) * DIM + k];           // warp-broadcast
            acc[u][0] += a * b.x;
            acc[u][1] += a * b.y;
            acc[u][2] += a * b.z;
            acc[u][3] += a * b.w;
        }
    }

    float4* gO = (float4*)(Og + (size_t)c * CHUNK * DIM);
#pragma unroll
    for (int u = 0; u < 8; u++)
        gO[(t0 + u) * (DIM / 4) + lane] =
            make_float4(acc[u][0], acc[u][1], acc[u][2], acc[u][3]);
}

// ---------------------------------------------------------------------------
extern "C" void kernel_launch(void* const* d_in, const int* in_sizes, int n_in,
                              void* d_out, int out_size) {
    const float* q  = (const float*)d_in[0];
    const float* k  = (const float*)d_in[1];
    const float* v  = (const float*)d_in[2];
    // d_in[3] = cu_seqlens (int32) — fixed 8 equal sequences, folded into CPS.
    const float* M0 = (const float*)d_in[4];
    float* o = (float*)d_out;

    const int SMEM1 = 2 * CHUNK * DIM * (int)sizeof(float);                       // 64 KB
    const int SMEM3 = (2 * CHUNK * DIM + DIM * KT_PITCH + CHUNK * S_PITCH)
                      * (int)sizeof(float);                                        // ~113 KB

    cudaFuncSetAttribute(la_kv_kernel,   cudaFuncAttributeMaxDynamicSharedMemorySize, SMEM1);
    cudaFuncSetAttribute(la_attn_kernel, cudaFuncAttributeMaxDynamicSharedMemorySize, SMEM3);

    la_kv_kernel<<<NCHUNK, 256, SMEM1>>>(k, v);
    la_prefix_kernel<<<dim3(DIM * DIM / 4 / 128, 8), 128>>>(M0);
    la_attn_kernel<<<NCHUNK, 256, SMEM3>>>(q, k, v, o);
}

// round 2
// speedup vs baseline: 1.4006x; 1.4006x over previous
#include <cuda_runtime.h>

#define T_TOTAL 8192
#define DIM     128
#define CHUNK   64
#define NCHUNK  (T_TOTAL / CHUNK)   // 128 chunks
#define CPS     16                  // chunks per sequence (1024 / 64)

#define KT_PITCH 65                 // scalar-access pitch (conflict-free)
#define S_PITCH  68                 // float4-aligned pitch for sS rows

// Scratch (no cudaMalloc allowed): per-chunk Gram matrices and prefix states.
__device__ float g_G[NCHUNK][DIM][DIM];    // K_c^T V_c            (8 MB)
__device__ float g_Min[NCHUNK][DIM][DIM];  // state entering chunk (8 MB)

// ---------------------------------------------------------------------------
// Kernel 1: G_c = K_c^T V_c for every chunk. 128 blocks x 512 threads.
// Warp wid owns output rows wid*8..wid*8+7; lane owns cols lane*4..lane*4+3.
// Per t: 2 broadcast LDS.128 (K row segment) + 1 streamed LDS.128 (V) + 32 FFMA.
// ---------------------------------------------------------------------------
__global__ void __launch_bounds__(512) la_kv_kernel(const float* __restrict__ Kg,
                                                    const float* __restrict__ Vg) {
    extern __shared__ float sm[];
    float* sK = sm;                 // [CHUNK][DIM]
    float* sV = sm + CHUNK * DIM;   // [CHUNK][DIM]
    const int c    = blockIdx.x;
    const int tid  = threadIdx.x;
    const int wid  = tid >> 5;
    const int lane = tid & 31;

    const float4* gk = (const float4*)(Kg + (size_t)c * CHUNK * DIM);
    const float4* gv = (const float4*)(Vg + (size_t)c * CHUNK * DIM);
#pragma unroll
    for (int i = tid; i < CHUNK * DIM / 4; i += 512) {
        ((float4*)sK)[i] = gk[i];
        ((float4*)sV)[i] = gv[i];
    }
    __syncthreads();

    const int r0 = wid * 8;
    float acc[8][4];
#pragma unroll
    for (int u = 0; u < 8; u++)
#pragma unroll
        for (int w = 0; w < 4; w++) acc[u][w] = 0.f;

#pragma unroll 8
    for (int t = 0; t < CHUNK; ++t) {
        float4 alo = *(const float4*)&sK[t * DIM + r0];      // broadcast
        float4 ahi = *(const float4*)&sK[t * DIM + r0 + 4];  // broadcast
        float4 b   = *(const float4*)&sV[t * DIM + lane * 4];
        float a[8] = {alo.x, alo.y, alo.z, alo.w, ahi.x, ahi.y, ahi.z, ahi.w};
#pragma unroll
        for (int u = 0; u < 8; u++) {
            acc[u][0] += a[u] * b.x;
            acc[u][1] += a[u] * b.y;
            acc[u][2] += a[u] * b.z;
            acc[u][3] += a[u] * b.w;
        }
    }

#pragma unroll
    for (int u = 0; u < 8; u++)
        ((float4*)&g_G[c][r0 + u][0])[lane] =
            make_float4(acc[u][0], acc[u][1], acc[u][2], acc[u][3]);
}

// ---------------------------------------------------------------------------
// Kernel 2: per-sequence prefix sum of G into M_in (M_in[first chunk] = M_0).
// grid = (32, 8): 8 sequences x (4096 float4 elements / 128 threads).
// ---------------------------------------------------------------------------
__global__ void __launch_bounds__(128) la_prefix_kernel(const float* __restrict__ M0) {
    const int e  = blockIdx.x * 128 + threadIdx.x;  // float4 element index 0..4095
    const int c0 = blockIdx.y * CPS;                // first chunk of this sequence
    float4 m = ((const float4*)M0)[e];
#pragma unroll
    for (int cl = 0; cl < CPS; ++cl) {
        ((float4*)&g_Min[c0 + cl][0][0])[e] = m;
        float4 g = ((const float4*)&g_G[c0 + cl][0][0])[e];
        m.x += g.x; m.y += g.y; m.z += g.z; m.w += g.w;
    }
}

// ---------------------------------------------------------------------------
// Kernel 3: per chunk  O = Q*M_in + tril_incl(Q K^T) * V.  128 blocks x 512 thr.
// Warp wid owns output rows wid*4..wid*4+3; lane owns cols lane*4..lane*4+3.
// Phase A: S = masked Q K^T (K transposed in smem).
// Phase B: O = S*V + Q*M_in, reduction dims stepped by 4 (float4 broadcasts).
// ---------------------------------------------------------------------------
__global__ void __launch_bounds__(512) la_attn_kernel(const float* __restrict__ Qg,
                                                      const float* __restrict__ Kg,
                                                      const float* __restrict__ Vg,
                                                      float* __restrict__ Og) {
    extern __shared__ float sm[];
    float* sQ  = sm;                       // [64][128]
    float* sV  = sQ + CHUNK * DIM;         // [64][128]
    float* sKt = sV + CHUNK * DIM;         // [128][KT_PITCH]  K transposed
    float* sS  = sKt + DIM * KT_PITCH;     // [64][S_PITCH]    masked scores

    const int c    = blockIdx.x;
    const int tid  = threadIdx.x;
    const int wid  = tid >> 5;
    const int lane = tid & 31;

    const float4* gq = (const float4*)(Qg + (size_t)c * CHUNK * DIM);
    const float4* gv = (const float4*)(Vg + (size_t)c * CHUNK * DIM);
    const float4* gk = (const float4*)(Kg + (size_t)c * CHUNK * DIM);

#pragma unroll
    for (int i = tid; i < CHUNK * DIM / 4; i += 512) {
        ((float4*)sQ)[i] = gq[i];
        ((float4*)sV)[i] = gv[i];
    }
    // K transposed into smem: sKt[k][t] = K[t][k]
#pragma unroll
    for (int f = tid; f < CHUNK * DIM / 4; f += 512) {
        int t  = f >> 5;              // token row (32 float4 per row)
        int k0 = (f & 31) << 2;       // feature base
        float4 kv = gk[f];
        sKt[(k0 + 0) * KT_PITCH + t] = kv.x;
        sKt[(k0 + 1) * KT_PITCH + t] = kv.y;
        sKt[(k0 + 2) * KT_PITCH + t] = kv.z;
        sKt[(k0 + 3) * KT_PITCH + t] = kv.w;
    }
    __syncthreads();

    const int t0 = wid * 4;           // this warp's 4 output rows

    // --- Phase A: S[t][s] = sum_k Q[t][k] K[s][k], inclusive causal (s <= t)
    {
        float accA[4][2];
#pragma unroll
        for (int u = 0; u < 4; u++) { accA[u][0] = 0.f; accA[u][1] = 0.f; }

#pragma unroll 4
        for (int k = 0; k < DIM; k += 4) {
            float4 q4[4];
#pragma unroll
            for (int u = 0; u < 4; u++)
                q4[u] = *(const float4*)&sQ[(t0 + u) * DIM + k];  // broadcast
#pragma unroll
            for (int i = 0; i < 4; i++) {
                float b0 = sKt[(k + i) * KT_PITCH + lane];
                float b1 = sKt[(k + i) * KT_PITCH + 32 + lane];
#pragma unroll
                for (int u = 0; u < 4; u++) {
                    float a = ((const float*)&q4[u])[i];
                    accA[u][0] += a * b0;
                    accA[u][1] += a * b1;
                }
            }
        }
#pragma unroll
        for (int u = 0; u < 4; u++) {
            int t = t0 + u;
            sS[t * S_PITCH + lane]      = (lane <= t)        ? accA[u][0] : 0.f;
            sS[t * S_PITCH + 32 + lane] = ((32 + lane) <= t) ? accA[u][1] : 0.f;
        }
    }
    // No __syncthreads needed: Phase B reads only sS rows this warp wrote.

    // --- Phase B: O[t][j] = sum_s S[t][s] V[s][j] + sum_k Q[t][k] Min[k][j]
    float acc[4][4];
#pragma unroll
    for (int u = 0; u < 4; u++)
#pragma unroll
        for (int w = 0; w < 4; w++) acc[u][w] = 0.f;

#pragma unroll 4
    for (int s = 0; s < CHUNK; s += 4) {
        float4 a4[4];
#pragma unroll
        for (int u = 0; u < 4; u++)
            a4[u] = *(const float4*)&sS[(t0 + u) * S_PITCH + s];  // broadcast
#pragma unroll
        for (int i = 0; i < 4; i++) {
            float4 b = *(const float4*)&sV[(s + i) * DIM + lane * 4];
#pragma unroll
            for (int u = 0; u < 4; u++) {
                float a = ((const float*)&a4[u])[i];
                acc[u][0] += a * b.x;
                acc[u][1] += a * b.y;
                acc[u][2] += a * b.z;
                acc[u][3] += a * b.w;
            }
        }
    }

    const float4* gM = (const float4*)&g_Min[c][0][0];
#pragma unroll 4
    for (int k = 0; k < DIM; k += 4) {
        float4 a4[4];
#pragma unroll
        for (int u = 0; u < 4; u++)
            a4[u] = *(const float4*)&sQ[(t0 + u) * DIM + k];      // broadcast
#pragma unroll
        for (int i = 0; i < 4; i++) {
            float4 b = gM[(k + i) * (DIM / 4) + lane];            // L1-hot
#pragma unroll
            for (int u = 0; u < 4; u++) {
                float a = ((const float*)&a4[u])[i];
                acc[u][0] += a * b.x;
                acc[u][1] += a * b.y;
                acc[u][2] += a * b.z;
                acc[u][3] += a * b.w;
            }
        }
    }

    float4* gO = (float4*)(Og + (size_t)c * CHUNK * DIM);
#pragma unroll
    for (int u = 0; u < 4; u++)
        gO[(t0 + u) * (DIM / 4) + lane] =
            make_float4(acc[u][0], acc[u][1], acc[u][2], acc[u][3]);
}

// ---------------------------------------------------------------------------
extern "C" void kernel_launch(void* const* d_in, const int* in_sizes, int n_in,
                              void* d_out, int out_size) {
    const float* q  = (const float*)d_in[0];
    const float* k  = (const float*)d_in[1];
    const float* v  = (const float*)d_in[2];
    // d_in[3] = cu_seqlens (int32) — fixed 8 equal sequences, folded into CPS.
    const float* M0 = (const float*)d_in[4];
    float* o = (float*)d_out;

    const int SMEM1 = 2 * CHUNK * DIM * (int)sizeof(float);                       // 64 KB
    const int SMEM3 = (2 * CHUNK * DIM + DIM * KT_PITCH + CHUNK * S_PITCH)
                      * (int)sizeof(float);                                        // ~114 KB

    cudaFuncSetAttribute(la_kv_kernel,   cudaFuncAttributeMaxDynamicSharedMemorySize, SMEM1);
    cudaFuncSetAttribute(la_attn_kernel, cudaFuncAttributeMaxDynamicSharedMemorySize, SMEM3);

    la_kv_kernel<<<NCHUNK, 512, SMEM1>>>(k, v);
    la_prefix_kernel<<<dim3(DIM * DIM / 4 / 128, 8), 128>>>(M0);
    la_attn_kernel<<<NCHUNK, 512, SMEM3>>>(q, k, v, o);
}